// round 1
// baseline (speedup 1.0000x reference)
#include <cuda_runtime.h>
#include <math.h>

// Problem constants
#define NPTS    524288
#define EMB     32
#define DIRD    27
#define FEAT    15
#define LAT     128
#define DH      64
#define OCC_OUT 16        // 1 + GEO_FEAT
#define RGB_IN_PT (EMB + DIRD + FEAT)   // 74 point-dependent inputs to rgb layer 0

#define TPB 256

// Shared-memory layout (floats)
#define S_OCCW0  0                       // 32*64   = 2048
#define S_OCCB0  (S_OCCW0 + EMB*DH)      // 64
#define S_OCCW1  (S_OCCB0 + DH)          // 64*64   = 4096
#define S_OCCB1  (S_OCCW1 + DH*DH)       // 64
#define S_OCCW2  (S_OCCB1 + DH)          // 64*16   = 1024
#define S_OCCB2  (S_OCCW2 + DH*OCC_OUT)  // 16
#define S_RGBW0  (S_OCCB2 + OCC_OUT)     // 202*64  = 12928
#define S_RGBB0  (S_RGBW0 + 202*DH)      // 64
#define S_RGBW1  (S_RGBB0 + DH)          // 64*64   = 4096
#define S_RGBB1  (S_RGBW1 + DH*DH)       // 64
#define S_RGBW2  (S_RGBB1 + DH)          // 64*3    = 192
#define S_RGBB2  (S_RGBW2 + DH*3)        // 3
#define S_LATB   (S_RGBB2 + 3)           // 64 (precomputed latent contribution + rgb_b0)
#define S_TOTAL  (S_LATB + DH)           // total floats
// S_TOTAL = 24723 floats = 98892 bytes

__device__ __forceinline__ float softplus_f(float x) {
    // stable softplus; for x>20, log1p(exp(x)) == x to fp32 precision
    if (x > 20.0f) return x;
    return log1pf(__expf(x));
}

__device__ __forceinline__ float sigmoid_f(float x) {
    return 1.0f / (1.0f + __expf(-x));
}

__global__ __launch_bounds__(TPB, 1)
void nerf_mlp_kernel(
    const float* __restrict__ embedded,       // (N,32)
    const float* __restrict__ embedded_dir,   // (N,27)
    const float* __restrict__ occ_W0, const float* __restrict__ occ_b0,
    const float* __restrict__ occ_W1, const float* __restrict__ occ_b1,
    const float* __restrict__ occ_W2, const float* __restrict__ occ_b2,
    const float* __restrict__ rgb_W0, const float* __restrict__ rgb_b0,
    const float* __restrict__ rgb_W1, const float* __restrict__ rgb_b1,
    const float* __restrict__ rgb_W2, const float* __restrict__ rgb_b2,
    const float* __restrict__ rgb_latent,     // (100,128)
    const int*   __restrict__ latent_index,
    float* __restrict__ out)                  // raw (N,4) then occ (N,)
{
    extern __shared__ float smem[];
    const int tid = threadIdx.x;

    // ---- cooperative weight staging into smem ----
    for (int t = tid; t < EMB*DH;      t += TPB) smem[S_OCCW0 + t] = occ_W0[t];
    for (int t = tid; t < DH;          t += TPB) smem[S_OCCB0 + t] = occ_b0[t];
    for (int t = tid; t < DH*DH;       t += TPB) smem[S_OCCW1 + t] = occ_W1[t];
    for (int t = tid; t < DH;          t += TPB) smem[S_OCCB1 + t] = occ_b1[t];
    for (int t = tid; t < DH*OCC_OUT;  t += TPB) smem[S_OCCW2 + t] = occ_W2[t];
    for (int t = tid; t < OCC_OUT;     t += TPB) smem[S_OCCB2 + t] = occ_b2[t];
    for (int t = tid; t < 202*DH;      t += TPB) smem[S_RGBW0 + t] = rgb_W0[t];
    for (int t = tid; t < DH;          t += TPB) smem[S_RGBB0 + t] = rgb_b0[t];
    for (int t = tid; t < DH*DH;       t += TPB) smem[S_RGBW1 + t] = rgb_W1[t];
    for (int t = tid; t < DH;          t += TPB) smem[S_RGBB1 + t] = rgb_b1[t];
    for (int t = tid; t < DH*3;        t += TPB) smem[S_RGBW2 + t] = rgb_W2[t];
    for (int t = tid; t < 3;           t += TPB) smem[S_RGBB2 + t] = rgb_b2[t];
    __syncthreads();

    // ---- fold constant latent vector into rgb layer-0 bias (per block) ----
    if (tid < DH) {
        const int li = *latent_index;
        const float* lrow = rgb_latent + li * LAT;
        float acc = smem[S_RGBB0 + tid];
        #pragma unroll 8
        for (int k = 0; k < LAT; k++)
            acc += lrow[k] * smem[S_RGBW0 + (RGB_IN_PT + k) * DH + tid];
        smem[S_LATB + tid] = acc;
    }
    __syncthreads();

    const int i = blockIdx.x * TPB + tid;
    if (i >= NPTS) return;

    // ---- load per-point embedding ----
    float e[EMB];
    {
        const float4* e4 = reinterpret_cast<const float4*>(embedded + (size_t)i * EMB);
        #pragma unroll
        for (int q = 0; q < EMB/4; q++) {
            float4 v = e4[q];
            e[q*4+0] = v.x; e[q*4+1] = v.y; e[q*4+2] = v.z; e[q*4+3] = v.w;
        }
    }

    // ---- occ layer 0: 32 -> 64, softplus ----
    float h[DH];
    #pragma unroll
    for (int j = 0; j < DH; j++) {
        float acc = smem[S_OCCB0 + j];
        #pragma unroll
        for (int k = 0; k < EMB; k++)
            acc = fmaf(e[k], smem[S_OCCW0 + k*DH + j], acc);
        h[j] = softplus_f(acc);
    }

    // ---- occ layer 1: 64 -> 64, softplus ----
    float g[DH];
    #pragma unroll
    for (int j = 0; j < DH; j++) {
        float acc = smem[S_OCCB1 + j];
        #pragma unroll
        for (int k = 0; k < DH; k++)
            acc = fmaf(h[k], smem[S_OCCW1 + k*DH + j], acc);
        g[j] = softplus_f(acc);
    }

    // ---- occ layer 2: 64 -> 16 (linear) ----
    float hid[OCC_OUT];
    #pragma unroll
    for (int j = 0; j < OCC_OUT; j++) {
        float acc = smem[S_OCCB2 + j];
        #pragma unroll
        for (int k = 0; k < DH; k++)
            acc = fmaf(g[k], smem[S_OCCW2 + k*OCC_OUT + j], acc);
        hid[j] = acc;
    }
    const float occ = 1.0f - __expf(-softplus_f(hid[0]));

    // ---- load direction embedding ----
    float d[DIRD];
    {
        const float* dp = embedded_dir + (size_t)i * DIRD;
        #pragma unroll
        for (int k = 0; k < DIRD; k++) d[k] = dp[k];
    }

    // ---- rgb layer 0: 74 point-dependent dims (+ precomputed latent bias), softplus ----
    float r[DH];
    #pragma unroll
    for (int j = 0; j < DH; j++) {
        float acc = smem[S_LATB + j];
        #pragma unroll
        for (int k = 0; k < EMB; k++)
            acc = fmaf(e[k], smem[S_RGBW0 + k*DH + j], acc);
        #pragma unroll
        for (int k = 0; k < DIRD; k++)
            acc = fmaf(d[k], smem[S_RGBW0 + (EMB + k)*DH + j], acc);
        #pragma unroll
        for (int k = 0; k < FEAT; k++)
            acc = fmaf(hid[1 + k], smem[S_RGBW0 + (EMB + DIRD + k)*DH + j], acc);
        r[j] = softplus_f(acc);
    }

    // ---- rgb layer 1: 64 -> 64, softplus ----
    float r2[DH];
    #pragma unroll
    for (int j = 0; j < DH; j++) {
        float acc = smem[S_RGBB1 + j];
        #pragma unroll
        for (int k = 0; k < DH; k++)
            acc = fmaf(r[k], smem[S_RGBW1 + k*DH + j], acc);
        r2[j] = softplus_f(acc);
    }

    // ---- rgb layer 2: 64 -> 3, sigmoid ----
    float rgb[3];
    #pragma unroll
    for (int j = 0; j < 3; j++) {
        float acc = smem[S_RGBB2 + j];
        #pragma unroll
        for (int k = 0; k < DH; k++)
            acc = fmaf(r2[k], smem[S_RGBW2 + k*3 + j], acc);
        rgb[j] = sigmoid_f(acc);
    }

    // ---- write outputs: raw (N,4) = [rgb, occ], then occ (N,) ----
    float4 raw = make_float4(rgb[0], rgb[1], rgb[2], occ);
    reinterpret_cast<float4*>(out)[i] = raw;
    out[(size_t)NPTS * 4 + i] = occ;
}

extern "C" void kernel_launch(void* const* d_in, const int* in_sizes, int n_in,
                              void* d_out, int out_size) {
    const float* embedded     = (const float*)d_in[0];
    const float* embedded_dir = (const float*)d_in[1];
    const float* occ_W0 = (const float*)d_in[2];
    const float* occ_b0 = (const float*)d_in[3];
    const float* occ_W1 = (const float*)d_in[4];
    const float* occ_b1 = (const float*)d_in[5];
    const float* occ_W2 = (const float*)d_in[6];
    const float* occ_b2 = (const float*)d_in[7];
    const float* rgb_W0 = (const float*)d_in[8];
    const float* rgb_b0 = (const float*)d_in[9];
    const float* rgb_W1 = (const float*)d_in[10];
    const float* rgb_b1 = (const float*)d_in[11];
    const float* rgb_W2 = (const float*)d_in[12];
    const float* rgb_b2 = (const float*)d_in[13];
    const float* rgb_latent = (const float*)d_in[14];
    const int*   latent_index = (const int*)d_in[15];

    const size_t smem_bytes = (size_t)S_TOTAL * sizeof(float);
    cudaFuncSetAttribute(nerf_mlp_kernel,
                         cudaFuncAttributeMaxDynamicSharedMemorySize,
                         (int)smem_bytes);

    dim3 grid(NPTS / TPB);
    dim3 block(TPB);
    nerf_mlp_kernel<<<grid, block, smem_bytes>>>(
        embedded, embedded_dir,
        occ_W0, occ_b0, occ_W1, occ_b1, occ_W2, occ_b2,
        rgb_W0, rgb_b0, rgb_W1, rgb_b1, rgb_W2, rgb_b2,
        rgb_latent, latent_index,
        (float*)d_out);
}

// round 2
// speedup vs baseline: 1.4792x; 1.4792x over previous
#include <cuda_runtime.h>

// ---------------- problem constants ----------------
#define NPTS   524288
#define TILE   128
#define NTILES (NPTS / TILE)     // 4096
#define TPB    512
#define NCTA   148
#define PADP   132               // padded point stride in smem activation buffers

#define DH   64
#define EMB  32
#define DIRD 27
#define FEAT 15
#define LAT  128
#define RGBK (EMB + DIRD + FEAT) // 74

// ---------------- smem layout (float offsets) ----------------
#define S_OCCW0 0
#define S_OCCW1 (S_OCCW0 + 32*64)   // 2048
#define S_OCCW2 (S_OCCW1 + 64*64)   // 6144
#define S_RGBW0 (S_OCCW2 + 64*16)   // 7168   (only first 74 rows)
#define S_RGBW1 (S_RGBW0 + 74*64)   // 11904
#define S_RGBW2 (S_RGBW1 + 64*64)   // 16000
#define S_OCCB0 (S_RGBW2 + 64*3)    // 16192
#define S_OCCB1 (S_OCCB0 + 64)      // 16256
#define S_OCCB2 (S_OCCB1 + 64)      // 16320
#define S_RGBB1 (S_OCCB2 + 16)      // 16336
#define S_RGBB2 (S_RGBB1 + 64)      // 16400
#define S_LATB  (S_RGBB2 + 4)       // 16404  (rgb_b0 + latent @ rgb_W0[74:202])
#define S_OCCV  (S_LATB + 64)       // 16468  (per-tile occ values, 128)
#define S_XB    (S_OCCV + 128)      // 16596  [74][PADP]  e | dir | feat
#define S_HB    (S_XB + 74*PADP)    // 26364  [64][PADP]
#define S_GB    (S_HB + 64*PADP)    // 34812  [64][PADP]
#define S_TOTAL (S_GB + 64*PADP)    // 43260 floats = 173040 bytes

__device__ __forceinline__ float sp_fast(float x) {
    // softplus = log(1 + exp(x)); fast MUFU path, guarded for large x
    float e = __expf(x);
    float y = __logf(1.0f + e);
    return (x > 20.0f) ? x : y;
}

__device__ __forceinline__ float sigmoid_fast(float x) {
    return 1.0f / (1.0f + __expf(-x));
}

// Generic dense layer: Y[128 x 64] = act(X[128 x K] @ W[K x 64] + b)
// X stored transposed in smem: X[k][p], stride PADP. W row-major [K][64].
// Thread tile: 2 points x 8 neurons.
template<int K, bool ACT>
__device__ __forceinline__ void layer64(float* sm, int xoff, int woff, int boff,
                                        int yoff, int tid)
{
    const int ty = tid >> 3;   // 0..63 -> points 2*ty, 2*ty+1
    const int tx = tid & 7;    // neurons 8*tx .. 8*tx+7
    const float* xp = sm + xoff + 2 * ty;
    const float* wp = sm + woff + 8 * tx;

    float a0[8], a1[8];
    {
        float4 b0 = *(const float4*)(sm + boff + 8 * tx);
        float4 b1 = *(const float4*)(sm + boff + 8 * tx + 4);
        a0[0] = b0.x; a0[1] = b0.y; a0[2] = b0.z; a0[3] = b0.w;
        a0[4] = b1.x; a0[5] = b1.y; a0[6] = b1.z; a0[7] = b1.w;
        #pragma unroll
        for (int n = 0; n < 8; n++) a1[n] = a0[n];
    }

    #pragma unroll 8
    for (int k = 0; k < K; k++) {
        float2 xv = *(const float2*)(xp + k * PADP);
        float4 w0 = *(const float4*)(wp + k * 64);
        float4 w1 = *(const float4*)(wp + k * 64 + 4);
        a0[0] = fmaf(xv.x, w0.x, a0[0]);  a1[0] = fmaf(xv.y, w0.x, a1[0]);
        a0[1] = fmaf(xv.x, w0.y, a0[1]);  a1[1] = fmaf(xv.y, w0.y, a1[1]);
        a0[2] = fmaf(xv.x, w0.z, a0[2]);  a1[2] = fmaf(xv.y, w0.z, a1[2]);
        a0[3] = fmaf(xv.x, w0.w, a0[3]);  a1[3] = fmaf(xv.y, w0.w, a1[3]);
        a0[4] = fmaf(xv.x, w1.x, a0[4]);  a1[4] = fmaf(xv.y, w1.x, a1[4]);
        a0[5] = fmaf(xv.x, w1.y, a0[5]);  a1[5] = fmaf(xv.y, w1.y, a1[5]);
        a0[6] = fmaf(xv.x, w1.z, a0[6]);  a1[6] = fmaf(xv.y, w1.z, a1[6]);
        a0[7] = fmaf(xv.x, w1.w, a0[7]);  a1[7] = fmaf(xv.y, w1.w, a1[7]);
    }

    float* yp = sm + yoff + 2 * ty;
    #pragma unroll
    for (int n = 0; n < 8; n++) {
        float u = a0[n], v = a1[n];
        if (ACT) { u = sp_fast(u); v = sp_fast(v); }
        *(float2*)(yp + (8 * tx + n) * PADP) = make_float2(u, v);
    }
}

__global__ __launch_bounds__(TPB, 1)
void nerf_mlp_gemm_kernel(
    const float* __restrict__ embedded,       // (N,32)
    const float* __restrict__ embedded_dir,   // (N,27)
    const float* __restrict__ occ_W0, const float* __restrict__ occ_b0,
    const float* __restrict__ occ_W1, const float* __restrict__ occ_b1,
    const float* __restrict__ occ_W2, const float* __restrict__ occ_b2,
    const float* __restrict__ rgb_W0, const float* __restrict__ rgb_b0,
    const float* __restrict__ rgb_W1, const float* __restrict__ rgb_b1,
    const float* __restrict__ rgb_W2, const float* __restrict__ rgb_b2,
    const float* __restrict__ rgb_latent,     // (100,128)
    const int*   __restrict__ latent_index,
    float* __restrict__ out)                  // raw (N,4) then occ (N,)
{
    extern __shared__ float sm[];
    const int tid = threadIdx.x;

    // ---------- stage weights once (persistent CTA) ----------
    for (int t = tid; t < 32*64;  t += TPB) sm[S_OCCW0 + t] = occ_W0[t];
    for (int t = tid; t < 64*64;  t += TPB) sm[S_OCCW1 + t] = occ_W1[t];
    for (int t = tid; t < 64*16;  t += TPB) sm[S_OCCW2 + t] = occ_W2[t];
    for (int t = tid; t < 74*64;  t += TPB) sm[S_RGBW0 + t] = rgb_W0[t];
    for (int t = tid; t < 64*64;  t += TPB) sm[S_RGBW1 + t] = rgb_W1[t];
    for (int t = tid; t < 64*3;   t += TPB) sm[S_RGBW2 + t] = rgb_W2[t];
    if (tid < 64) sm[S_OCCB0 + tid] = occ_b0[tid];
    if (tid >= 64  && tid < 128) sm[S_OCCB1 + tid - 64]  = occ_b1[tid - 64];
    if (tid >= 128 && tid < 144) sm[S_OCCB2 + tid - 128] = occ_b2[tid - 128];
    if (tid >= 144 && tid < 208) sm[S_RGBB1 + tid - 144] = rgb_b1[tid - 144];
    if (tid >= 208 && tid < 211) sm[S_RGBB2 + tid - 208] = rgb_b2[tid - 208];

    // fold constant latent vector into rgb layer-0 bias
    if (tid >= 256 && tid < 320) {
        const int j = tid - 256;
        const int li = *latent_index;
        const float* lrow = rgb_latent + li * LAT;
        float acc = rgb_b0[j];
        #pragma unroll 8
        for (int l = 0; l < LAT; l++)
            acc = fmaf(lrow[l], rgb_W0[(RGBK + l) * 64 + j], acc);
        sm[S_LATB + j] = acc;
    }
    __syncthreads();

    // ---------- persistent tile loop ----------
    for (int tile = blockIdx.x; tile < NTILES; tile += NCTA) {
        const int g0 = tile * TILE;   // first point of this tile

        // load embedded (transposed) -> XB rows 0..31
        {
            const float* src = embedded + (size_t)g0 * EMB;
            for (int idx = tid; idx < TILE * EMB; idx += TPB) {
                int p = idx >> 5, k = idx & 31;
                sm[S_XB + k * PADP + p] = src[idx];
            }
        }
        // load embedded_dir -> XB rows 32..58
        {
            const float* src = embedded_dir + (size_t)g0 * DIRD;
            for (int idx = tid; idx < TILE * DIRD; idx += TPB) {
                int p = idx / DIRD, k = idx - p * DIRD;
                sm[S_XB + (EMB + k) * PADP + p] = src[idx];
            }
        }
        __syncthreads();

        // occ layer 0: 32 -> 64, softplus
        layer64<EMB, true>(sm, S_XB, S_OCCW0, S_OCCB0, S_HB, tid);
        __syncthreads();
        // occ layer 1: 64 -> 64, softplus
        layer64<DH, true>(sm, S_HB, S_OCCW1, S_OCCB1, S_GB, tid);
        __syncthreads();

        // occ layer 2: 64 -> 16 (linear). 4 outputs per thread.
        {
            const int p  = tid >> 2;        // 0..127
            const int n0 = (tid & 3) * 4;   // 0,4,8,12
            float4 b = *(const float4*)(sm + S_OCCB2 + n0);
            float acc[4] = {b.x, b.y, b.z, b.w};
            const float* xp = sm + S_GB + p;
            const float* wp = sm + S_OCCW2 + n0;
            #pragma unroll 8
            for (int k = 0; k < DH; k++) {
                float x = xp[k * PADP];
                float4 w = *(const float4*)(wp + k * 16);
                acc[0] = fmaf(x, w.x, acc[0]);
                acc[1] = fmaf(x, w.y, acc[1]);
                acc[2] = fmaf(x, w.z, acc[2]);
                acc[3] = fmaf(x, w.w, acc[3]);
            }
            #pragma unroll
            for (int j = 0; j < 4; j++) {
                int n = n0 + j;
                if (n == 0) {
                    float o = 1.0f - __expf(-sp_fast(acc[0]));
                    sm[S_OCCV + p] = o;
                    out[(size_t)NPTS * 4 + g0 + p] = o;   // occ output
                } else {
                    sm[S_XB + (EMB + DIRD + n - 1) * PADP + p] = acc[j]; // feature
                }
            }
        }
        __syncthreads();

        // rgb layer 0: 74 -> 64, softplus (bias = latent-folded)
        layer64<RGBK, true>(sm, S_XB, S_RGBW0, S_LATB, S_HB, tid);
        __syncthreads();
        // rgb layer 1: 64 -> 64, softplus
        layer64<DH, true>(sm, S_HB, S_RGBW1, S_RGBB1, S_GB, tid);
        __syncthreads();

        // rgb layer 2: 64 -> 3, sigmoid; write raw float4
        if (tid < TILE) {
            const int p = tid;
            float a0 = sm[S_RGBB2 + 0];
            float a1 = sm[S_RGBB2 + 1];
            float a2 = sm[S_RGBB2 + 2];
            const float* xp = sm + S_GB + p;
            const float* wp = sm + S_RGBW2;
            #pragma unroll 8
            for (int k = 0; k < DH; k++) {
                float x = xp[k * PADP];
                a0 = fmaf(x, wp[k * 3 + 0], a0);
                a1 = fmaf(x, wp[k * 3 + 1], a1);
                a2 = fmaf(x, wp[k * 3 + 2], a2);
            }
            float4 raw = make_float4(sigmoid_fast(a0), sigmoid_fast(a1),
                                     sigmoid_fast(a2), sm[S_OCCV + p]);
            reinterpret_cast<float4*>(out)[g0 + p] = raw;
        }
        __syncthreads();   // protect GB/XB/OCCV before next tile overwrites
    }
}

extern "C" void kernel_launch(void* const* d_in, const int* in_sizes, int n_in,
                              void* d_out, int out_size) {
    const float* embedded     = (const float*)d_in[0];
    const float* embedded_dir = (const float*)d_in[1];
    const float* occ_W0 = (const float*)d_in[2];
    const float* occ_b0 = (const float*)d_in[3];
    const float* occ_W1 = (const float*)d_in[4];
    const float* occ_b1 = (const float*)d_in[5];
    const float* occ_W2 = (const float*)d_in[6];
    const float* occ_b2 = (const float*)d_in[7];
    const float* rgb_W0 = (const float*)d_in[8];
    const float* rgb_b0 = (const float*)d_in[9];
    const float* rgb_W1 = (const float*)d_in[10];
    const float* rgb_b1 = (const float*)d_in[11];
    const float* rgb_W2 = (const float*)d_in[12];
    const float* rgb_b2 = (const float*)d_in[13];
    const float* rgb_latent = (const float*)d_in[14];
    const int*   latent_index = (const int*)d_in[15];

    const size_t smem_bytes = (size_t)S_TOTAL * sizeof(float);
    static int configured = 0;
    cudaFuncSetAttribute(nerf_mlp_gemm_kernel,
                         cudaFuncAttributeMaxDynamicSharedMemorySize,
                         (int)smem_bytes);
    (void)configured;

    nerf_mlp_gemm_kernel<<<NCTA, TPB, smem_bytes>>>(
        embedded, embedded_dir,
        occ_W0, occ_b0, occ_W1, occ_b1, occ_W2, occ_b2,
        rgb_W0, rgb_b0, rgb_W1, rgb_b1, rgb_W2, rgb_b2,
        rgb_latent, latent_index,
        (float*)d_out);
}

// round 4
// speedup vs baseline: 2.2493x; 1.5206x over previous
#include <cuda_runtime.h>

// ---------------- problem constants ----------------
#define NPTS   524288
#define TILE   128
#define NTILES (NPTS / TILE)     // 4096
#define TPB    256
#define NCTA   148
#define PADP   132               // padded point stride in smem activation buffers

#define DH   64
#define EMB  32
#define DIRD 27
#define FEAT 15
#define LAT  128
#define RGBK (EMB + DIRD + FEAT) // 74

// ---------------- smem layout (float offsets) ----------------
#define S_OCCW0 0
#define S_OCCW1 (S_OCCW0 + 32*64)   // 2048
#define S_OCCW2 (S_OCCW1 + 64*64)   // 6144
#define S_RGBW0 (S_OCCW2 + 64*16)   // 7168   (only first 74 rows)
#define S_RGBW1 (S_RGBW0 + 74*64)   // 11904
#define S_RGBW2 (S_RGBW1 + 64*64)   // 16000
#define S_OCCB0 (S_RGBW2 + 64*3)    // 16192
#define S_OCCB1 (S_OCCB0 + 64)      // 16256
#define S_OCCB2 (S_OCCB1 + 64)      // 16320
#define S_RGBB1 (S_OCCB2 + 16)      // 16336
#define S_RGBB2 (S_RGBB1 + 64)      // 16400
#define S_LATB  (S_RGBB2 + 4)       // 16404  (rgb_b0 + latent @ rgb_W0[74:202])
#define S_OCCV  (S_LATB + 64)       // 16468
#define S_XB    (S_OCCV + 128)      // 16596  [74][PADP]
#define S_HB    (S_XB + 74*PADP)    // 26364  [64][PADP]
#define S_GB    (S_HB + 64*PADP)    // 34812  [64][PADP]
#define S_TOTAL (S_GB + 64*PADP)    // 43260 floats = 173040 bytes

typedef unsigned long long u64t;

#define FMA_F32X2(d, a, b, c) \
    asm("fma.rn.f32x2 %0, %1, %2, %3;" : "=l"(d) : "l"(a), "l"(b), "l"(c))
#define PACK_SPLAT(out, x) \
    asm("mov.b64 %0, {%1, %1};" : "=l"(out) : "r"(__float_as_uint(x)))
#define UNPACK_F32X2U(lo, hi, in) \
    asm("mov.b64 {%0, %1}, %2;" : "=r"(lo), "=r"(hi) : "l"(in))

__device__ __forceinline__ float sp_fast(float x) {
    float e = __expf(x);
    float y = __logf(1.0f + e);
    return (x > 20.0f) ? x : y;
}
__device__ __forceinline__ float sigmoid_fast(float x) {
    return 1.0f / (1.0f + __expf(-x));
}

// Dense layer Y[128 x 64] = act(X[128 x K] @ W[K x 64] + b)
// X transposed in smem X[k][p] (stride PADP); W row-major [K][64].
// Thread tile: 4 points x 8 neurons, neuron-pair-packed f32x2 accumulators.
template<int K, bool ACT>
__device__ __forceinline__ void layer64_f2(float* sm, int xoff, int woff,
                                           int boff, int yoff, int tid)
{
    const int ty = tid >> 3;   // 0..31 : points 4*ty .. 4*ty+3
    const int tx = tid & 7;    // neurons 8*tx .. 8*tx+7
    const float* xp = sm + xoff + 4 * ty;
    const float* wp = sm + woff + 8 * tx;

    u64t acc[4][4];            // [pt][neuron-pair]
    {
        const u64t* bp = (const u64t*)(sm + boff + 8 * tx);
        u64t b0 = bp[0], b1 = bp[1], b2 = bp[2], b3 = bp[3];
        #pragma unroll
        for (int p = 0; p < 4; p++) {
            acc[p][0] = b0; acc[p][1] = b1; acc[p][2] = b2; acc[p][3] = b3;
        }
    }

    #pragma unroll 8
    for (int k = 0; k < K; k++) {
        float4 xv = *(const float4*)(xp + k * PADP);
        u64t xs0, xs1, xs2, xs3;
        PACK_SPLAT(xs0, xv.x); PACK_SPLAT(xs1, xv.y);
        PACK_SPLAT(xs2, xv.z); PACK_SPLAT(xs3, xv.w);
        ulonglong2 wA = *(const ulonglong2*)(wp + k * 64);      // n pairs 0,1
        ulonglong2 wB = *(const ulonglong2*)(wp + k * 64 + 4);  // n pairs 2,3
        FMA_F32X2(acc[0][0], xs0, wA.x, acc[0][0]);
        FMA_F32X2(acc[0][1], xs0, wA.y, acc[0][1]);
        FMA_F32X2(acc[0][2], xs0, wB.x, acc[0][2]);
        FMA_F32X2(acc[0][3], xs0, wB.y, acc[0][3]);
        FMA_F32X2(acc[1][0], xs1, wA.x, acc[1][0]);
        FMA_F32X2(acc[1][1], xs1, wA.y, acc[1][1]);
        FMA_F32X2(acc[1][2], xs1, wB.x, acc[1][2]);
        FMA_F32X2(acc[1][3], xs1, wB.y, acc[1][3]);
        FMA_F32X2(acc[2][0], xs2, wA.x, acc[2][0]);
        FMA_F32X2(acc[2][1], xs2, wA.y, acc[2][1]);
        FMA_F32X2(acc[2][2], xs2, wB.x, acc[2][2]);
        FMA_F32X2(acc[2][3], xs2, wB.y, acc[2][3]);
        FMA_F32X2(acc[3][0], xs3, wA.x, acc[3][0]);
        FMA_F32X2(acc[3][1], xs3, wA.y, acc[3][1]);
        FMA_F32X2(acc[3][2], xs3, wB.x, acc[3][2]);
        FMA_F32X2(acc[3][3], xs3, wB.y, acc[3][3]);
    }

    // unpack, activate, store: per neuron a float4 of 4 consecutive points
    float vals[4][8];
    #pragma unroll
    for (int p = 0; p < 4; p++) {
        #pragma unroll
        for (int np = 0; np < 4; np++) {
            unsigned int ulo, uhi;
            UNPACK_F32X2U(ulo, uhi, acc[p][np]);
            float lo = __uint_as_float(ulo);
            float hi = __uint_as_float(uhi);
            if (ACT) { lo = sp_fast(lo); hi = sp_fast(hi); }
            vals[p][2*np]   = lo;
            vals[p][2*np+1] = hi;
        }
    }
    float* yp = sm + yoff + 4 * ty;
    #pragma unroll
    for (int n = 0; n < 8; n++) {
        *(float4*)(yp + (8 * tx + n) * PADP) =
            make_float4(vals[0][n], vals[1][n], vals[2][n], vals[3][n]);
    }
}

__global__ __launch_bounds__(TPB, 1)
void nerf_mlp_gemm_kernel(
    const float* __restrict__ embedded,       // (N,32)
    const float* __restrict__ embedded_dir,   // (N,27)
    const float* __restrict__ occ_W0, const float* __restrict__ occ_b0,
    const float* __restrict__ occ_W1, const float* __restrict__ occ_b1,
    const float* __restrict__ occ_W2, const float* __restrict__ occ_b2,
    const float* __restrict__ rgb_W0, const float* __restrict__ rgb_b0,
    const float* __restrict__ rgb_W1, const float* __restrict__ rgb_b1,
    const float* __restrict__ rgb_W2, const float* __restrict__ rgb_b2,
    const float* __restrict__ rgb_latent,     // (100,128)
    const int*   __restrict__ latent_index,
    float* __restrict__ out)                  // raw (N,4) then occ (N,)
{
    extern __shared__ float sm[];
    const int tid = threadIdx.x;

    // ---------- stage weights once (persistent CTA) ----------
    for (int t = tid; t < 32*64;  t += TPB) sm[S_OCCW0 + t] = occ_W0[t];
    for (int t = tid; t < 64*64;  t += TPB) sm[S_OCCW1 + t] = occ_W1[t];
    for (int t = tid; t < 64*16;  t += TPB) sm[S_OCCW2 + t] = occ_W2[t];
    for (int t = tid; t < 74*64;  t += TPB) sm[S_RGBW0 + t] = rgb_W0[t];
    for (int t = tid; t < 64*64;  t += TPB) sm[S_RGBW1 + t] = rgb_W1[t];
    for (int t = tid; t < 64*3;   t += TPB) sm[S_RGBW2 + t] = rgb_W2[t];
    if (tid < 64) sm[S_OCCB0 + tid] = occ_b0[tid];
    if (tid >= 64  && tid < 128) sm[S_OCCB1 + tid - 64]  = occ_b1[tid - 64];
    if (tid >= 128 && tid < 144) sm[S_OCCB2 + tid - 128] = occ_b2[tid - 128];
    if (tid >= 144 && tid < 208) sm[S_RGBB1 + tid - 144] = rgb_b1[tid - 144];
    if (tid >= 208 && tid < 211) sm[S_RGBB2 + tid - 208] = rgb_b2[tid - 208];

    // fold constant latent into rgb layer-0 bias (reads globals only)
    if (tid >= 192) {
        const int j = tid - 192;
        const int li = *latent_index;
        const float* lrow = rgb_latent + li * LAT;
        float acc = rgb_b0[j];
        #pragma unroll 8
        for (int l = 0; l < LAT; l++)
            acc = fmaf(lrow[l], rgb_W0[(RGBK + l) * 64 + j], acc);
        sm[S_LATB + j] = acc;
    }
    __syncthreads();

    // ---------- persistent tile loop ----------
    for (int tile = blockIdx.x; tile < NTILES; tile += NCTA) {
        const int g0 = tile * TILE;

        // load embedded (transposed) -> XB rows 0..31
        {
            const float* src = embedded + (size_t)g0 * EMB;
            for (int idx = tid; idx < TILE * EMB; idx += TPB) {
                int p = idx >> 5, k = idx & 31;
                sm[S_XB + k * PADP + p] = src[idx];
            }
        }
        // embedded_dir -> XB rows 32..58
        {
            const float* src = embedded_dir + (size_t)g0 * DIRD;
            for (int idx = tid; idx < TILE * DIRD; idx += TPB) {
                int p = idx / DIRD, k = idx - p * DIRD;
                sm[S_XB + (EMB + k) * PADP + p] = src[idx];
            }
        }
        __syncthreads();

        // occ layer 0: 32 -> 64, softplus
        layer64_f2<EMB, true>(sm, S_XB, S_OCCW0, S_OCCB0, S_HB, tid);
        __syncthreads();
        // occ layer 1: 64 -> 64, softplus
        layer64_f2<DH, true>(sm, S_HB, S_OCCW1, S_OCCB1, S_GB, tid);
        __syncthreads();

        // occ layer 2: 64 -> 16 (linear). 8 outputs per thread, 2 thr/point.
        {
            const int p    = tid >> 1;          // 0..127
            const int n0   = (tid & 1) * 8;     // 0 or 8
            float acc[8];
            {
                const float4* b4 = (const float4*)(sm + S_OCCB2 + n0);
                float4 b0 = b4[0], b1 = b4[1];
                acc[0]=b0.x; acc[1]=b0.y; acc[2]=b0.z; acc[3]=b0.w;
                acc[4]=b1.x; acc[5]=b1.y; acc[6]=b1.z; acc[7]=b1.w;
            }
            const float* xp = sm + S_GB + p;
            const float* wp = sm + S_OCCW2 + n0;
            #pragma unroll 8
            for (int k = 0; k < DH; k++) {
                float x = xp[k * PADP];
                float4 w0 = *(const float4*)(wp + k * 16);
                float4 w1 = *(const float4*)(wp + k * 16 + 4);
                acc[0] = fmaf(x, w0.x, acc[0]);
                acc[1] = fmaf(x, w0.y, acc[1]);
                acc[2] = fmaf(x, w0.z, acc[2]);
                acc[3] = fmaf(x, w0.w, acc[3]);
                acc[4] = fmaf(x, w1.x, acc[4]);
                acc[5] = fmaf(x, w1.y, acc[5]);
                acc[6] = fmaf(x, w1.z, acc[6]);
                acc[7] = fmaf(x, w1.w, acc[7]);
            }
            #pragma unroll
            for (int j = 0; j < 8; j++) {
                int n = n0 + j;
                if (n == 0) {
                    float o = 1.0f - __expf(-sp_fast(acc[0]));
                    sm[S_OCCV + p] = o;
                    out[(size_t)NPTS * 4 + g0 + p] = o;
                } else {
                    sm[S_XB + (EMB + DIRD + n - 1) * PADP + p] = acc[j];
                }
            }
        }
        __syncthreads();

        // rgb layer 0: 74 -> 64, softplus (bias = latent-folded)
        layer64_f2<RGBK, true>(sm, S_XB, S_RGBW0, S_LATB, S_HB, tid);
        __syncthreads();
        // rgb layer 1: 64 -> 64, softplus
        layer64_f2<DH, true>(sm, S_HB, S_RGBW1, S_RGBB1, S_GB, tid);
        __syncthreads();

        // rgb layer 2: 64 -> 3, sigmoid; write raw float4
        if (tid < TILE) {
            const int p = tid;
            float a0 = sm[S_RGBB2 + 0];
            float a1 = sm[S_RGBB2 + 1];
            float a2 = sm[S_RGBB2 + 2];
            const float* xp = sm + S_GB + p;
            const float* wp = sm + S_RGBW2;
            #pragma unroll 8
            for (int k = 0; k < DH; k++) {
                float x = xp[k * PADP];
                a0 = fmaf(x, wp[k * 3 + 0], a0);
                a1 = fmaf(x, wp[k * 3 + 1], a1);
                a2 = fmaf(x, wp[k * 3 + 2], a2);
            }
            float4 raw = make_float4(sigmoid_fast(a0), sigmoid_fast(a1),
                                     sigmoid_fast(a2), sm[S_OCCV + p]);
            reinterpret_cast<float4*>(out)[g0 + p] = raw;
        }
        __syncthreads();
    }
}

extern "C" void kernel_launch(void* const* d_in, const int* in_sizes, int n_in,
                              void* d_out, int out_size) {
    const float* embedded     = (const float*)d_in[0];
    const float* embedded_dir = (const float*)d_in[1];
    const float* occ_W0 = (const float*)d_in[2];
    const float* occ_b0 = (const float*)d_in[3];
    const float* occ_W1 = (const float*)d_in[4];
    const float* occ_b1 = (const float*)d_in[5];
    const float* occ_W2 = (const float*)d_in[6];
    const float* occ_b2 = (const float*)d_in[7];
    const float* rgb_W0 = (const float*)d_in[8];
    const float* rgb_b0 = (const float*)d_in[9];
    const float* rgb_W1 = (const float*)d_in[10];
    const float* rgb_b1 = (const float*)d_in[11];
    const float* rgb_W2 = (const float*)d_in[12];
    const float* rgb_b2 = (const float*)d_in[13];
    const float* rgb_latent = (const float*)d_in[14];
    const int*   latent_index = (const int*)d_in[15];

    const size_t smem_bytes = (size_t)S_TOTAL * sizeof(float);
    cudaFuncSetAttribute(nerf_mlp_gemm_kernel,
                         cudaFuncAttributeMaxDynamicSharedMemorySize,
                         (int)smem_bytes);

    nerf_mlp_gemm_kernel<<<NCTA, TPB, smem_bytes>>>(
        embedded, embedded_dir,
        occ_W0, occ_b0, occ_W1, occ_b1, occ_W2, occ_b2,
        rgb_W0, rgb_b0, rgb_W1, rgb_b1, rgb_W2, rgb_b2,
        rgb_latent, latent_index,
        (float*)d_out);
}

// round 5
// speedup vs baseline: 2.3121x; 1.0279x over previous
#include <cuda_runtime.h>

// ---------------- problem constants ----------------
#define NPTS   524288
#define TILE   128
#define NTILES (NPTS / TILE)     // 4096
#define TPB    128
#define NCTA   148
#define PADP   132               // padded point stride in smem activation buffers

#define DH   64
#define EMB  32
#define DIRD 27
#define FEAT 15
#define LAT  128
#define RGBK (EMB + DIRD + FEAT) // 74

// ---------------- smem layout (float offsets) ----------------
#define S_OCCW0 0
#define S_OCCW1 (S_OCCW0 + 32*64)   // 2048
#define S_OCCW2 (S_OCCW1 + 64*64)   // 6144
#define S_RGBW0 (S_OCCW2 + 64*16)   // 7168   (only first 74 rows)
#define S_RGBW1 (S_RGBW0 + 74*64)   // 11904
#define S_RGBW2 (S_RGBW1 + 64*64)   // 16000
#define S_OCCB0 (S_RGBW2 + 64*3)    // 16192
#define S_OCCB1 (S_OCCB0 + 64)      // 16256
#define S_OCCB2 (S_OCCB1 + 64)      // 16320
#define S_RGBB1 (S_OCCB2 + 16)      // 16336
#define S_RGBB2 (S_RGBB1 + 64)      // 16400
#define S_LATB  (S_RGBB2 + 4)       // 16404  (rgb_b0 + latent @ rgb_W0[74:202])
#define S_OCCV  (S_LATB + 64)       // 16468
#define S_XB    (S_OCCV + 128)      // 16596  [74][PADP]
#define S_HB    (S_XB + 74*PADP)    // 26364  [64][PADP]
#define S_GB    (S_HB + 64*PADP)    // 34812  [64][PADP]
#define S_TOTAL (S_GB + 64*PADP)    // 43260 floats = 173040 bytes

typedef unsigned long long u64t;

#define FMA_F32X2(d, a, b, c) \
    asm("fma.rn.f32x2 %0, %1, %2, %3;" : "=l"(d) : "l"(a), "l"(b), "l"(c))
#define PACK_SPLAT(out, x) \
    asm("mov.b64 %0, {%1, %1};" : "=l"(out) : "r"(__float_as_uint(x)))
#define UNPACK_F32X2U(lo, hi, in) \
    asm("mov.b64 {%0, %1}, %2;" : "=r"(lo), "=r"(hi) : "l"(in))

__device__ __forceinline__ float sp_fast(float x) {
    float e = __expf(x);
    float y = __logf(1.0f + e);
    return (x > 20.0f) ? x : y;
}
__device__ __forceinline__ float sigmoid_fast(float x) {
    return 1.0f / (1.0f + __expf(-x));
}

// Dense layer Y[128 x 64] = act(X[128 x K] @ W[K x 64] + b)
// X transposed in smem X[k][p] (stride PADP); W row-major [K][64].
// Thread tile: 8 points x 8 neurons, neuron-pair-packed f32x2 accumulators.
template<int K, bool ACT>
__device__ __forceinline__ void layer64_f2(float* sm, int xoff, int woff,
                                           int boff, int yoff, int tid)
{
    const int ty = tid >> 3;   // 0..15 : points 8*ty .. 8*ty+7
    const int tx = tid & 7;    // neurons 8*tx .. 8*tx+7
    const float* xp = sm + xoff + 8 * ty;
    const float* wp = sm + woff + 8 * tx;

    u64t acc[8][4];            // [pt][neuron-pair]
    {
        const u64t* bp = (const u64t*)(sm + boff + 8 * tx);
        u64t b0 = bp[0], b1 = bp[1], b2 = bp[2], b3 = bp[3];
        #pragma unroll
        for (int p = 0; p < 8; p++) {
            acc[p][0] = b0; acc[p][1] = b1; acc[p][2] = b2; acc[p][3] = b3;
        }
    }

    #pragma unroll 4
    for (int k = 0; k < K; k++) {
        float4 xa = *(const float4*)(xp + k * PADP);
        float4 xb = *(const float4*)(xp + k * PADP + 4);
        u64t xs[8];
        PACK_SPLAT(xs[0], xa.x); PACK_SPLAT(xs[1], xa.y);
        PACK_SPLAT(xs[2], xa.z); PACK_SPLAT(xs[3], xa.w);
        PACK_SPLAT(xs[4], xb.x); PACK_SPLAT(xs[5], xb.y);
        PACK_SPLAT(xs[6], xb.z); PACK_SPLAT(xs[7], xb.w);
        ulonglong2 wA = *(const ulonglong2*)(wp + k * 64);      // n pairs 0,1
        ulonglong2 wB = *(const ulonglong2*)(wp + k * 64 + 4);  // n pairs 2,3
        #pragma unroll
        for (int p = 0; p < 8; p++) {
            FMA_F32X2(acc[p][0], xs[p], wA.x, acc[p][0]);
            FMA_F32X2(acc[p][1], xs[p], wA.y, acc[p][1]);
            FMA_F32X2(acc[p][2], xs[p], wB.x, acc[p][2]);
            FMA_F32X2(acc[p][3], xs[p], wB.y, acc[p][3]);
        }
    }

    // unpack, activate, store: per neuron two float4s of 8 consecutive points
    float vals[8][8];   // [pt][n]
    #pragma unroll
    for (int p = 0; p < 8; p++) {
        #pragma unroll
        for (int np = 0; np < 4; np++) {
            unsigned int ulo, uhi;
            UNPACK_F32X2U(ulo, uhi, acc[p][np]);
            float lo = __uint_as_float(ulo);
            float hi = __uint_as_float(uhi);
            if (ACT) { lo = sp_fast(lo); hi = sp_fast(hi); }
            vals[p][2*np]   = lo;
            vals[p][2*np+1] = hi;
        }
    }
    float* yp = sm + yoff + 8 * ty;
    #pragma unroll
    for (int n = 0; n < 8; n++) {
        *(float4*)(yp + (8 * tx + n) * PADP) =
            make_float4(vals[0][n], vals[1][n], vals[2][n], vals[3][n]);
        *(float4*)(yp + (8 * tx + n) * PADP + 4) =
            make_float4(vals[4][n], vals[5][n], vals[6][n], vals[7][n]);
    }
}

__global__ __launch_bounds__(TPB, 1)
void nerf_mlp_gemm_kernel(
    const float* __restrict__ embedded,       // (N,32)
    const float* __restrict__ embedded_dir,   // (N,27)
    const float* __restrict__ occ_W0, const float* __restrict__ occ_b0,
    const float* __restrict__ occ_W1, const float* __restrict__ occ_b1,
    const float* __restrict__ occ_W2, const float* __restrict__ occ_b2,
    const float* __restrict__ rgb_W0, const float* __restrict__ rgb_b0,
    const float* __restrict__ rgb_W1, const float* __restrict__ rgb_b1,
    const float* __restrict__ rgb_W2, const float* __restrict__ rgb_b2,
    const float* __restrict__ rgb_latent,     // (100,128)
    const int*   __restrict__ latent_index,
    float* __restrict__ out)                  // raw (N,4) then occ (N,)
{
    extern __shared__ float sm[];
    const int tid = threadIdx.x;

    // ---------- stage weights once (persistent CTA) ----------
    for (int t = tid; t < 32*64;  t += TPB) sm[S_OCCW0 + t] = occ_W0[t];
    for (int t = tid; t < 64*64;  t += TPB) sm[S_OCCW1 + t] = occ_W1[t];
    for (int t = tid; t < 64*16;  t += TPB) sm[S_OCCW2 + t] = occ_W2[t];
    for (int t = tid; t < 74*64;  t += TPB) sm[S_RGBW0 + t] = rgb_W0[t];
    for (int t = tid; t < 64*64;  t += TPB) sm[S_RGBW1 + t] = rgb_W1[t];
    for (int t = tid; t < 64*3;   t += TPB) sm[S_RGBW2 + t] = rgb_W2[t];
    for (int t = tid; t < 64; t += TPB) {
        sm[S_OCCB0 + t] = occ_b0[t];
        sm[S_OCCB1 + t] = occ_b1[t];
        sm[S_RGBB1 + t] = rgb_b1[t];
    }
    if (tid < 16) sm[S_OCCB2 + tid] = occ_b2[tid];
    if (tid >= 16 && tid < 19) sm[S_RGBB2 + tid - 16] = rgb_b2[tid - 16];

    // fold constant latent into rgb layer-0 bias (reads globals only)
    if (tid >= 64) {
        const int j = tid - 64;
        const int li = *latent_index;
        const float* lrow = rgb_latent + li * LAT;
        float acc = rgb_b0[j];
        #pragma unroll 8
        for (int l = 0; l < LAT; l++)
            acc = fmaf(lrow[l], rgb_W0[(RGBK + l) * 64 + j], acc);
        sm[S_LATB + j] = acc;
    }
    __syncthreads();

    // ---------- persistent tile loop ----------
    for (int tile = blockIdx.x; tile < NTILES; tile += NCTA) {
        const int g0 = tile * TILE;

        // load embedded (transposed) -> XB rows 0..31
        {
            const float* src = embedded + (size_t)g0 * EMB;
            for (int idx = tid; idx < TILE * EMB; idx += TPB) {
                int p = idx >> 5, k = idx & 31;
                sm[S_XB + k * PADP + p] = src[idx];
            }
        }
        // embedded_dir -> XB rows 32..58
        {
            const float* src = embedded_dir + (size_t)g0 * DIRD;
            for (int idx = tid; idx < TILE * DIRD; idx += TPB) {
                int p = idx / DIRD, k = idx - p * DIRD;
                sm[S_XB + (EMB + k) * PADP + p] = src[idx];
            }
        }
        __syncthreads();

        // occ layer 0: 32 -> 64, softplus
        layer64_f2<EMB, true>(sm, S_XB, S_OCCW0, S_OCCB0, S_HB, tid);
        __syncthreads();
        // occ layer 1: 64 -> 64, softplus
        layer64_f2<DH, true>(sm, S_HB, S_OCCW1, S_OCCB1, S_GB, tid);
        __syncthreads();

        // occ layer 2: 64 -> 16 (linear). One thread per point, 16 outputs.
        {
            const int p = tid;
            float acc[16];
            {
                #pragma unroll
                for (int q = 0; q < 4; q++) {
                    float4 b = *(const float4*)(sm + S_OCCB2 + 4*q);
                    acc[4*q+0]=b.x; acc[4*q+1]=b.y; acc[4*q+2]=b.z; acc[4*q+3]=b.w;
                }
            }
            const float* xp = sm + S_GB + p;
            const float* wp = sm + S_OCCW2;
            #pragma unroll 4
            for (int k = 0; k < DH; k++) {
                float x = xp[k * PADP];
                #pragma unroll
                for (int q = 0; q < 4; q++) {
                    float4 w = *(const float4*)(wp + k * 16 + 4*q);
                    acc[4*q+0] = fmaf(x, w.x, acc[4*q+0]);
                    acc[4*q+1] = fmaf(x, w.y, acc[4*q+1]);
                    acc[4*q+2] = fmaf(x, w.z, acc[4*q+2]);
                    acc[4*q+3] = fmaf(x, w.w, acc[4*q+3]);
                }
            }
            float o = 1.0f - __expf(-sp_fast(acc[0]));
            sm[S_OCCV + p] = o;
            out[(size_t)NPTS * 4 + g0 + p] = o;
            #pragma unroll
            for (int n = 1; n < 16; n++)
                sm[S_XB + (EMB + DIRD + n - 1) * PADP + p] = acc[n];
        }
        __syncthreads();

        // rgb layer 0: 74 -> 64, softplus (bias = latent-folded)
        layer64_f2<RGBK, true>(sm, S_XB, S_RGBW0, S_LATB, S_HB, tid);
        __syncthreads();
        // rgb layer 1: 64 -> 64, softplus
        layer64_f2<DH, true>(sm, S_HB, S_RGBW1, S_RGBB1, S_GB, tid);
        __syncthreads();

        // rgb layer 2: 64 -> 3, sigmoid; one thread per point
        {
            const int p = tid;
            float a0 = sm[S_RGBB2 + 0];
            float a1 = sm[S_RGBB2 + 1];
            float a2 = sm[S_RGBB2 + 2];
            const float* xp = sm + S_GB + p;
            const float* wp = sm + S_RGBW2;
            #pragma unroll 8
            for (int k = 0; k < DH; k++) {
                float x = xp[k * PADP];
                a0 = fmaf(x, wp[k * 3 + 0], a0);
                a1 = fmaf(x, wp[k * 3 + 1], a1);
                a2 = fmaf(x, wp[k * 3 + 2], a2);
            }
            float4 raw = make_float4(sigmoid_fast(a0), sigmoid_fast(a1),
                                     sigmoid_fast(a2), sm[S_OCCV + p]);
            reinterpret_cast<float4*>(out)[g0 + p] = raw;
        }
        __syncthreads();
    }
}

extern "C" void kernel_launch(void* const* d_in, const int* in_sizes, int n_in,
                              void* d_out, int out_size) {
    const float* embedded     = (const float*)d_in[0];
    const float* embedded_dir = (const float*)d_in[1];
    const float* occ_W0 = (const float*)d_in[2];
    const float* occ_b0 = (const float*)d_in[3];
    const float* occ_W1 = (const float*)d_in[4];
    const float* occ_b1 = (const float*)d_in[5];
    const float* occ_W2 = (const float*)d_in[6];
    const float* occ_b2 = (const float*)d_in[7];
    const float* rgb_W0 = (const float*)d_in[8];
    const float* rgb_b0 = (const float*)d_in[9];
    const float* rgb_W1 = (const float*)d_in[10];
    const float* rgb_b1 = (const float*)d_in[11];
    const float* rgb_W2 = (const float*)d_in[12];
    const float* rgb_b2 = (const float*)d_in[13];
    const float* rgb_latent = (const float*)d_in[14];
    const int*   latent_index = (const int*)d_in[15];

    const size_t smem_bytes = (size_t)S_TOTAL * sizeof(float);
    cudaFuncSetAttribute(nerf_mlp_gemm_kernel,
                         cudaFuncAttributeMaxDynamicSharedMemorySize,
                         (int)smem_bytes);

    nerf_mlp_gemm_kernel<<<NCTA, TPB, smem_bytes>>>(
        embedded, embedded_dir,
        occ_W0, occ_b0, occ_W1, occ_b1, occ_W2, occ_b2,
        rgb_W0, rgb_b0, rgb_W1, rgb_b1, rgb_W2, rgb_b2,
        rgb_latent, latent_index,
        (float*)d_out);
}